// round 1
// baseline (speedup 1.0000x reference)
#include <cuda_runtime.h>
#include <cuda_bf16.h>
#include <math.h>

// ---------------------------------------------------------------------------
// Problem constants: B=8, S=1024, D=1024, H=4096, TOP_K*S = 1048576
// ---------------------------------------------------------------------------
#define BATCH 8
#define SEQ   1024
#define DMODEL 1024
#define HID   4096
#define KSEL  1048576           // k for top-k (= 25% of SEQ*HID)
#define NPB   (SEQ * HID)       // elements per batch in score matrix (4194304)

// Scratch (device globals; no cudaMalloc allowed)
__device__ float    g_s1[BATCH * SEQ * HID];   // scores1 / reused as h (silu out)
__device__ float    g_s2[BATCH * SEQ * HID];   // scores2
__device__ unsigned g_colmax[BATCH * HID];     // monotone-uint column max
__device__ unsigned g_hist1[BATCH * 4096];
__device__ unsigned g_hist2[BATCH * 4096];
__device__ unsigned g_hist3[BATCH * 256];
__device__ unsigned g_selbits[BATCH];          // selected radix prefix
__device__ int      g_krem[BATCH];             // remaining rank
__device__ unsigned g_tau[BATCH];              // k-th largest (monotone uint)
__device__ unsigned char g_maskarr[BATCH * HID];

// ---------------------------------------------------------------------------
// Helpers
// ---------------------------------------------------------------------------
__device__ __forceinline__ unsigned mono(float f) {
    unsigned u = __float_as_uint(f);
    return (u & 0x80000000u) ? ~u : (u | 0x80000000u);
}

__device__ __forceinline__ unsigned to_tf32u(float x) {
    unsigned u;
    asm("cvt.rna.tf32.f32 %0, %1;" : "=r"(u) : "f"(x));
    return u;
}

__device__ __forceinline__ void mma_tf32(float* d, const unsigned* a, const unsigned* b) {
    asm volatile(
        "mma.sync.aligned.m16n8k8.row.col.f32.tf32.tf32.f32 "
        "{%0,%1,%2,%3}, {%4,%5,%6,%7}, {%8,%9}, {%0,%1,%2,%3};"
        : "+f"(d[0]), "+f"(d[1]), "+f"(d[2]), "+f"(d[3])
        : "r"(a[0]), "r"(a[1]), "r"(a[2]), "r"(a[3]), "r"(b[0]), "r"(b[1]));
}

// ---------------------------------------------------------------------------
// TF32 NT GEMM: C[m,n] = epilogue( sum_k A[m,k]*B[n,k] + bias[n] )
// A row-major [M,K], B row-major [N,K].
// MODE 0: relu(acc+bias)
// MODE 1: acc+bias
// MODE 2: per-batch (gridDim.z), B row selected by mask: silu(acc + bias_sel)
// Tiles: BM=BN=128, BK=32, 256 threads (8 warps as 4(m) x 2(n), warp tile 32x64)
// ---------------------------------------------------------------------------
template <int MODE>
__global__ void __launch_bounds__(256)
gemm_tf32(const float* __restrict__ A, const float* __restrict__ Bmat,
          const float* __restrict__ bias, float* __restrict__ C,
          int M, int N, int K,
          const float* __restrict__ B2mat, const float* __restrict__ bias2,
          const unsigned char* __restrict__ maskrow)
{
    __shared__ float As[32][132];
    __shared__ float Bs[32][132];

    const int tid  = threadIdx.x;
    const int lane = tid & 31;
    const int warp = tid >> 5;
    const int wm   = warp & 3;     // 4 warps along M (32 rows each)
    const int wn   = warp >> 2;    // 2 warps along N (64 cols each)
    const int tg   = lane & 3;     // thread-in-group
    const int gid  = lane >> 2;    // group id

    const int row0 = blockIdx.y * 128;
    const int col0 = blockIdx.x * 128;

    const unsigned char* mrow = nullptr;
    if (MODE == 2) {
        size_t b = blockIdx.z;
        A += b * (size_t)M * K;
        C += b * (size_t)M * N;
        mrow = maskrow + b * (size_t)N;
    }

    float acc[2][8][4];
#pragma unroll
    for (int mi = 0; mi < 2; mi++)
#pragma unroll
        for (int ni = 0; ni < 8; ni++)
#pragma unroll
            for (int j = 0; j < 4; j++) acc[mi][ni][j] = 0.f;

    for (int kt = 0; kt < K; kt += 32) {
        // ---- load A tile (128x32) ----
#pragma unroll
        for (int i = 0; i < 4; i++) {
            int lin = tid + i * 256;
            int r   = lin >> 3;
            int kc  = (lin & 7) << 2;
            float4 v = *reinterpret_cast<const float4*>(
                &A[(size_t)(row0 + r) * K + kt + kc]);
            As[kc + 0][r] = __uint_as_float(to_tf32u(v.x));
            As[kc + 1][r] = __uint_as_float(to_tf32u(v.y));
            As[kc + 2][r] = __uint_as_float(to_tf32u(v.z));
            As[kc + 3][r] = __uint_as_float(to_tf32u(v.w));
        }
        // ---- load B tile (128x32), per-row source select in MODE 2 ----
#pragma unroll
        for (int i = 0; i < 4; i++) {
            int lin = tid + i * 256;
            int r   = lin >> 3;
            int kc  = (lin & 7) << 2;
            int gn  = col0 + r;
            const float* src = Bmat;
            if (MODE == 2) { if (mrow[gn]) src = B2mat; }
            float4 v = *reinterpret_cast<const float4*>(
                &src[(size_t)gn * K + kt + kc]);
            Bs[kc + 0][r] = __uint_as_float(to_tf32u(v.x));
            Bs[kc + 1][r] = __uint_as_float(to_tf32u(v.y));
            Bs[kc + 2][r] = __uint_as_float(to_tf32u(v.z));
            Bs[kc + 3][r] = __uint_as_float(to_tf32u(v.w));
        }
        __syncthreads();

#pragma unroll
        for (int ks = 0; ks < 4; ks++) {
            const int k0 = ks * 8;
            unsigned a[2][4], bb[8][2];
#pragma unroll
            for (int mi = 0; mi < 2; mi++) {
                int mr = wm * 32 + mi * 16 + gid;
                a[mi][0] = __float_as_uint(As[k0 + tg][mr]);
                a[mi][1] = __float_as_uint(As[k0 + tg][mr + 8]);
                a[mi][2] = __float_as_uint(As[k0 + 4 + tg][mr]);
                a[mi][3] = __float_as_uint(As[k0 + 4 + tg][mr + 8]);
            }
#pragma unroll
            for (int ni = 0; ni < 8; ni++) {
                int nc = wn * 64 + ni * 8 + gid;
                bb[ni][0] = __float_as_uint(Bs[k0 + tg][nc]);
                bb[ni][1] = __float_as_uint(Bs[k0 + 4 + tg][nc]);
            }
#pragma unroll
            for (int mi = 0; mi < 2; mi++)
#pragma unroll
                for (int ni = 0; ni < 8; ni++)
                    mma_tf32(acc[mi][ni], a[mi], bb[ni]);
        }
        __syncthreads();
    }

    // ---- epilogue ----
#pragma unroll
    for (int mi = 0; mi < 2; mi++) {
#pragma unroll
        for (int ni = 0; ni < 8; ni++) {
            int r0 = row0 + wm * 32 + mi * 16 + gid;
            int c0 = col0 + wn * 64 + ni * 8 + tg * 2;
#pragma unroll
            for (int j = 0; j < 4; j++) {
                int r = r0 + ((j >= 2) ? 8 : 0);
                int c = c0 + (j & 1);
                float v = acc[mi][ni][j];
                if (MODE == 0) {
                    v = fmaxf(v + bias[c], 0.f);
                } else if (MODE == 1) {
                    v = v + bias[c];
                } else {
                    float bv = mrow[c] ? bias2[c] : bias[c];
                    v = v + bv;
                    v = v / (1.f + expf(-v));   // silu
                }
                C[(size_t)r * N + c] = v;
            }
        }
    }
}

// ---------------------------------------------------------------------------
// Column max (over s) + radix histogram pass 1 (top 12 bits), fused read.
// grid: BATCH*64 blocks of 256; each block covers 16 rows of one batch.
// ---------------------------------------------------------------------------
__global__ void __launch_bounds__(256)
colmax_hist1_kernel(const float* __restrict__ S2,
                    unsigned* __restrict__ colmax, unsigned* __restrict__ hist)
{
    __shared__ unsigned sh[4096];
    const int bb = blockIdx.x;
    const int b  = bb >> 6;
    const int s0 = (bb & 63) * 16;
    const int t  = threadIdx.x;

    for (int i = t; i < 4096; i += 256) sh[i] = 0;
    __syncthreads();

    float lm[16];
#pragma unroll
    for (int i = 0; i < 16; i++) lm[i] = -3.4e38f;

    for (int s = 0; s < 16; s++) {
        const float* row = S2 + ((size_t)b * SEQ + s0 + s) * HID;
#pragma unroll
        for (int hh = 0; hh < 16; hh++) {
            float f = row[hh * 256 + t];
            lm[hh] = fmaxf(lm[hh], f);
            atomicAdd(&sh[mono(f) >> 20], 1u);
        }
    }
#pragma unroll
    for (int hh = 0; hh < 16; hh++)
        atomicMax(&colmax[b * HID + hh * 256 + t], mono(lm[hh]));

    __syncthreads();
    for (int i = t; i < 4096; i += 256) {
        unsigned c = sh[i];
        if (c) atomicAdd(&hist[b * 4096 + i], c);
    }
}

// ---------------------------------------------------------------------------
// Radix histogram pass 2: mid 12 bits among elements matching top-12 prefix
// ---------------------------------------------------------------------------
__global__ void __launch_bounds__(256)
hist_pass2(const float* __restrict__ S2, const unsigned* __restrict__ sel,
           unsigned* __restrict__ hist)
{
    __shared__ unsigned sh[4096];
    const int b = blockIdx.y;
    const int t = threadIdx.x;
    for (int i = t; i < 4096; i += 256) sh[i] = 0;
    __syncthreads();
    const unsigned s1 = sel[b];
    const float4* p = reinterpret_cast<const float4*>(S2 + (size_t)b * NPB)
                      + (size_t)blockIdx.x * 16384;
    for (int i = 0; i < 64; i++) {
        float4 v = p[t + i * 256];
        unsigned u;
        u = mono(v.x); if ((u >> 20) == s1) atomicAdd(&sh[(u >> 8) & 0xFFF], 1u);
        u = mono(v.y); if ((u >> 20) == s1) atomicAdd(&sh[(u >> 8) & 0xFFF], 1u);
        u = mono(v.z); if ((u >> 20) == s1) atomicAdd(&sh[(u >> 8) & 0xFFF], 1u);
        u = mono(v.w); if ((u >> 20) == s1) atomicAdd(&sh[(u >> 8) & 0xFFF], 1u);
    }
    __syncthreads();
    for (int i = t; i < 4096; i += 256) {
        unsigned c = sh[i];
        if (c) atomicAdd(&hist[b * 4096 + i], c);
    }
}

// ---------------------------------------------------------------------------
// Radix histogram pass 3: low 8 bits among elements matching top-24 prefix
// ---------------------------------------------------------------------------
__global__ void __launch_bounds__(256)
hist_pass3(const float* __restrict__ S2, const unsigned* __restrict__ sel,
           unsigned* __restrict__ hist)
{
    __shared__ unsigned sh[256];
    const int b = blockIdx.y;
    const int t = threadIdx.x;
    sh[t] = 0;
    __syncthreads();
    const unsigned s24 = sel[b];
    const float4* p = reinterpret_cast<const float4*>(S2 + (size_t)b * NPB)
                      + (size_t)blockIdx.x * 16384;
    for (int i = 0; i < 64; i++) {
        float4 v = p[t + i * 256];
        unsigned u;
        u = mono(v.x); if ((u >> 8) == s24) atomicAdd(&sh[u & 0xFF], 1u);
        u = mono(v.y); if ((u >> 8) == s24) atomicAdd(&sh[u & 0xFF], 1u);
        u = mono(v.z); if ((u >> 8) == s24) atomicAdd(&sh[u & 0xFF], 1u);
        u = mono(v.w); if ((u >> 8) == s24) atomicAdd(&sh[u & 0xFF], 1u);
    }
    __syncthreads();
    unsigned c = sh[t];
    if (c) atomicAdd(&hist[b * 256 + t], c);
}

// ---------------------------------------------------------------------------
// Scan a per-batch histogram (descending) to locate the bin holding rank k.
// stage 1: k = KSEL, writes sel=bin, krem
// stage 2: k = krem, sel = (sel<<12)|bin, krem
// stage 3: k = krem, tau = (sel<<8)|bin  (exact k-th largest monotone uint)
// ---------------------------------------------------------------------------
__global__ void __launch_bounds__(256)
scan_kernel(const unsigned* __restrict__ hist, int nbins, int stage,
            unsigned* __restrict__ sel, int* __restrict__ krem,
            unsigned* __restrict__ tau)
{
    __shared__ int sS[256];
    __shared__ int sSuf[257];
    const int b = blockIdx.x;
    const int t = threadIdx.x;
    const int k = (stage == 1) ? KSEL : krem[b];
    const int chunk = nbins >> 8;
    const unsigned* h = hist + (size_t)b * nbins;

    int s = 0;
    for (int j = 0; j < chunk; j++) s += h[t * chunk + j];
    sS[t] = s;
    __syncthreads();
    if (t == 0) {
        sSuf[256] = 0;
        for (int i = 255; i >= 0; i--) sSuf[i] = sSuf[i + 1] + sS[i];
    }
    __syncthreads();
    if (sSuf[t] >= k && sSuf[t + 1] < k) {
        int cum = sSuf[t + 1];
        for (int j = chunk - 1; j >= 0; j--) {
            int bin = t * chunk + j;
            int c = (int)h[bin];
            cum += c;
            if (cum >= k) {
                int kp = k - (cum - c);
                if (stage == 1)      { sel[b] = (unsigned)bin; krem[b] = kp; }
                else if (stage == 2) { sel[b] = (sel[b] << 12) | (unsigned)bin; krem[b] = kp; }
                else                 { tau[b] = (sel[b] << 8) | (unsigned)bin; }
                break;
            }
        }
    }
}

__global__ void mask_kernel(const unsigned* __restrict__ colmax,
                            const unsigned* __restrict__ tau,
                            unsigned char* __restrict__ maskarr)
{
    int i = blockIdx.x * 256 + threadIdx.x;   // 32768 total
    maskarr[i] = (colmax[i] >= tau[i >> 12]) ? 1 : 0;
}

// ---------------------------------------------------------------------------
// Host launcher (graph-capturable: kernels + async memsets only)
// ---------------------------------------------------------------------------
extern "C" void kernel_launch(void* const* d_in, const int* in_sizes, int n_in,
                              void* d_out, int out_size)
{
    (void)in_sizes; (void)n_in; (void)out_size;
    const float* x     = (const float*)d_in[0];
    const float* up_w  = (const float*)d_in[1];
    const float* up_b  = (const float*)d_in[2];
    const float* gw1   = (const float*)d_in[3];
    const float* gb1   = (const float*)d_in[4];
    const float* gw2   = (const float*)d_in[5];
    const float* gb2   = (const float*)d_in[6];
    const float* mod_w = (const float*)d_in[7];
    const float* mod_b = (const float*)d_in[8];
    const float* dw    = (const float*)d_in[9];
    const float* db    = (const float*)d_in[10];
    float* out = (float*)d_out;

    void *pS1, *pS2, *pCol, *pH1, *pH2, *pH3, *pSel, *pK, *pTau, *pMask;
    cudaGetSymbolAddress(&pS1, g_s1);
    cudaGetSymbolAddress(&pS2, g_s2);
    cudaGetSymbolAddress(&pCol, g_colmax);
    cudaGetSymbolAddress(&pH1, g_hist1);
    cudaGetSymbolAddress(&pH2, g_hist2);
    cudaGetSymbolAddress(&pH3, g_hist3);
    cudaGetSymbolAddress(&pSel, g_selbits);
    cudaGetSymbolAddress(&pK, g_krem);
    cudaGetSymbolAddress(&pTau, g_tau);
    cudaGetSymbolAddress(&pMask, g_maskarr);

    cudaMemsetAsync(pCol, 0, BATCH * HID * 4, 0);
    cudaMemsetAsync(pH1, 0, BATCH * 4096 * 4, 0);
    cudaMemsetAsync(pH2, 0, BATCH * 4096 * 4, 0);
    cudaMemsetAsync(pH3, 0, BATCH * 256 * 4, 0);

    // GEMM1: S1 = relu(X @ gate_w1^T + gb1)   [8192,4096]
    gemm_tf32<0><<<dim3(32, 64, 1), 256>>>(
        x, gw1, gb1, (float*)pS1, BATCH * SEQ, HID, DMODEL,
        nullptr, nullptr, nullptr);
    // GEMM2: S2 = S1 @ gate_w2^T + gb2        [8192,4096]
    gemm_tf32<1><<<dim3(32, 64, 1), 256>>>(
        (float*)pS1, gw2, gb2, (float*)pS2, BATCH * SEQ, HID, HID,
        nullptr, nullptr, nullptr);

    // Exact k-th largest per batch via 3-pass radix select + column max
    colmax_hist1_kernel<<<BATCH * 64, 256>>>(
        (const float*)pS2, (unsigned*)pCol, (unsigned*)pH1);
    scan_kernel<<<BATCH, 256>>>((const unsigned*)pH1, 4096, 1,
                                (unsigned*)pSel, (int*)pK, (unsigned*)pTau);
    hist_pass2<<<dim3(64, BATCH), 256>>>(
        (const float*)pS2, (const unsigned*)pSel, (unsigned*)pH2);
    scan_kernel<<<BATCH, 256>>>((const unsigned*)pH2, 4096, 2,
                                (unsigned*)pSel, (int*)pK, (unsigned*)pTau);
    hist_pass3<<<dim3(64, BATCH), 256>>>(
        (const float*)pS2, (const unsigned*)pSel, (unsigned*)pH3);
    scan_kernel<<<BATCH, 256>>>((const unsigned*)pH3, 256, 3,
                                (unsigned*)pSel, (int*)pK, (unsigned*)pTau);
    mask_kernel<<<128, 256>>>((const unsigned*)pCol, (const unsigned*)pTau,
                              (unsigned char*)pMask);

    // GEMM3 (per batch): h = silu(X_b @ W_sel^T + b_sel) -> reuse g_s1
    gemm_tf32<2><<<dim3(32, 8, BATCH), 256>>>(
        x, up_w, up_b, (float*)pS1, SEQ, HID, DMODEL,
        mod_w, mod_b, (const unsigned char*)pMask);
    // GEMM4: out = h @ down_w^T + down_b      [8192,1024]
    gemm_tf32<1><<<dim3(8, 64, 1), 256>>>(
        (float*)pS1, dw, db, out, BATCH * SEQ, DMODEL, HID,
        nullptr, nullptr, nullptr);
}

// round 12
// speedup vs baseline: 1.7092x; 1.7092x over previous
#include <cuda_runtime.h>
#include <cuda_bf16.h>
#include <math.h>

// ---------------------------------------------------------------------------
// Problem constants: B=8, S=1024, D=1024, H=4096, TOP_K*S = 1048576
// ---------------------------------------------------------------------------
#define BATCH 8
#define SEQ   1024
#define DMODEL 1024
#define HID   4096
#define KSEL  1048576
#define NPB   (SEQ * HID)

// GEMM tiling: CTA 128x128, BK=32, 8 warps (4m x 2n), warp tile 32x64
#define BM 128
#define BN 128
#define BK 32
#define ASTRIDE 36                   // floats per smem row (BK + 4 pad)
#define AFLOATS (BM * ASTRIDE)       // 4608
#define BFLOATS (BN * ASTRIDE)       // 4608
#define STF (AFLOATS + BFLOATS)      // 9216 floats per stage
#define SMEM_BYTES (3 * STF * 4)     // 110592 B (2 CTAs/SM)

// ---------------------------------------------------------------------------
// Scratch (device globals; no cudaMalloc allowed)
// ---------------------------------------------------------------------------
__device__ __align__(256) float g_s1[BATCH * SEQ * HID];    // relu(gemm1), tf32-rounded
__device__ __align__(256) float g_s2[BATCH * SEQ * HID];    // scores2 fp32
__device__ __align__(256) float g_h [BATCH * SEQ * HID];    // silu(gemm3), tf32-rounded
__device__ __align__(256) float g_xr [BATCH * SEQ * DMODEL];
__device__ __align__(256) float g_g1r[HID * DMODEL];
__device__ __align__(256) float g_g2r[HID * HID];
__device__ __align__(256) float g_upr[HID * DMODEL];
__device__ __align__(256) float g_modr[HID * DMODEL];
__device__ __align__(256) float g_dwr[DMODEL * HID];

__device__ unsigned g_colmax[BATCH * HID];
__device__ unsigned g_hist1[BATCH * 4096];
__device__ unsigned g_hist2[BATCH * 4096];
__device__ unsigned g_hist3[BATCH * 256];
__device__ unsigned g_selbits[BATCH];
__device__ int      g_krem[BATCH];
__device__ unsigned g_tau[BATCH];
__device__ unsigned char g_maskarr[BATCH * HID];

// ---------------------------------------------------------------------------
// Helpers
// ---------------------------------------------------------------------------
__device__ __forceinline__ unsigned smem_u32(const void* p) {
    unsigned a;
    asm("{ .reg .u64 t; cvta.to.shared.u64 t, %1; cvt.u32.u64 %0, t; }"
        : "=r"(a) : "l"(p));
    return a;
}

__device__ __forceinline__ unsigned to_tf32u(float x) {
    unsigned u;
    asm("cvt.rna.tf32.f32 %0, %1;" : "=r"(u) : "f"(x));
    return u;
}

__device__ __forceinline__ float round_tf32(float x) {
    return __uint_as_float(to_tf32u(x));
}

__device__ __forceinline__ void cp16(unsigned s, const void* g) {
    asm volatile("cp.async.cg.shared.global [%0], [%1], 16;"
                 :: "r"(s), "l"(g) : "memory");
}

__device__ __forceinline__ void mma_tf32(float* d, const unsigned* a,
                                         unsigned b0, unsigned b1) {
    asm volatile(
        "mma.sync.aligned.m16n8k8.row.col.f32.tf32.tf32.f32 "
        "{%0,%1,%2,%3}, {%4,%5,%6,%7}, {%8,%9}, {%0,%1,%2,%3};"
        : "+f"(d[0]), "+f"(d[1]), "+f"(d[2]), "+f"(d[3])
        : "r"(a[0]), "r"(a[1]), "r"(a[2]), "r"(a[3]), "r"(b0), "r"(b1));
}

__device__ __forceinline__ unsigned mono(float f) {
    unsigned u = __float_as_uint(f);
    return (u & 0x80000000u) ? ~u : (u | 0x80000000u);
}

// ---------------------------------------------------------------------------
// One-shot fp32 -> tf32(RNA) rounding pass (vectorized)
// ---------------------------------------------------------------------------
__global__ void __launch_bounds__(256)
round4_kernel(const float4* __restrict__ s, float4* __restrict__ d, int n4)
{
    int i = blockIdx.x * 256 + threadIdx.x;
    if (i < n4) {
        float4 v = s[i];
        v.x = round_tf32(v.x);  v.y = round_tf32(v.y);
        v.z = round_tf32(v.z);  v.w = round_tf32(v.w);
        d[i] = v;
    }
}

// ---------------------------------------------------------------------------
// TF32 NT GEMM, 3-stage cp.async pipeline.
// C[m,n] = epi( sum_k A[m,k]*B[n,k] + bias[n] ).  A,B pre-rounded to tf32.
// MODE 0: relu -> tf32-rounded fp32    MODE 1: +bias fp32
// MODE 2: per-batch z; B row & bias by mask: silu -> tf32-rounded fp32
// ---------------------------------------------------------------------------
template <int MODE>
__global__ void __launch_bounds__(256, 2)
gemm_tf32(const float* __restrict__ A, const float* __restrict__ Bm,
          const float* __restrict__ B2, const float* __restrict__ bias,
          const float* __restrict__ bias2, const unsigned char* __restrict__ maskp,
          float* __restrict__ C, int M, int N, int K)
{
    extern __shared__ float sm[];
    const int tid = threadIdx.x, lane = tid & 31, wid = tid >> 5;
    const int wm = wid & 3, wn = wid >> 2;       // 4 warps M, 2 warps N
    const int gid = lane >> 2, tg = lane & 3;
    const int row0 = blockIdx.y * BM, col0 = blockIdx.x * BN;

    if (MODE == 2) {
        size_t z = blockIdx.z;
        A += z * (size_t)M * K;
        C += z * (size_t)M * N;
        maskp += z * (size_t)N;
    }

    // ---- cp.async source pointers + smem byte offsets (4+4 chunks/thread) --
    const float* gA[4]; unsigned sA[4];
    const float* gB[4]; unsigned sB[4];
#pragma unroll
    for (int j = 0; j < 4; j++) {
        int ca = tid + j * 256;                  // 1024 chunks of 16B for A
        int r = ca >> 3, c4 = ca & 7;
        sA[j] = (unsigned)((r * ASTRIDE + c4 * 4) * 4);
        gA[j] = A + (size_t)(row0 + r) * K + c4 * 4;
        int cb = ca;                             // 1024 chunks for B
        int rb = cb >> 3, c4b = cb & 7;
        sB[j] = (unsigned)((AFLOATS + rb * ASTRIDE + c4b * 4) * 4);
        const float* src = Bm;
        if (MODE == 2) { if (maskp[col0 + rb]) src = B2; }
        gB[j] = src + (size_t)(col0 + rb) * K + c4b * 4;
    }
    const unsigned smBase = smem_u32(sm);

    float acc[2][8][4];
#pragma unroll
    for (int mi = 0; mi < 2; mi++)
#pragma unroll
        for (int ni = 0; ni < 8; ni++)
#pragma unroll
            for (int j = 0; j < 4; j++) acc[mi][ni][j] = 0.f;

    const int KT = K / BK;

    auto load_stage = [&](int it) {
        if (it < KT) {
            unsigned st = smBase + (unsigned)(it % 3) * (STF * 4);
            int off = it * BK;
#pragma unroll
            for (int j = 0; j < 4; j++) cp16(st + sA[j], gA[j] + off);
#pragma unroll
            for (int j = 0; j < 4; j++) cp16(st + sB[j], gB[j] + off);
        }
        asm volatile("cp.async.commit_group;" ::: "memory");
    };

    load_stage(0);
    load_stage(1);

    // fragment row offsets (floats) within a stage
    int rowA[4], rowB[8];
#pragma unroll
    for (int mi = 0; mi < 2; mi++) {
        rowA[mi * 2 + 0] = (wm * 32 + mi * 16 + gid + 0) * ASTRIDE + tg;
        rowA[mi * 2 + 1] = (wm * 32 + mi * 16 + gid + 8) * ASTRIDE + tg;
    }
#pragma unroll
    for (int ni = 0; ni < 8; ni++)
        rowB[ni] = AFLOATS + (wn * 64 + ni * 8 + gid) * ASTRIDE + tg;

    for (int it = 0; it < KT; it++) {
        asm volatile("cp.async.wait_group 1;" ::: "memory");
        __syncthreads();
        load_stage(it + 2);
        const float* S = sm + (it % 3) * STF;
#pragma unroll
        for (int ks = 0; ks < 4; ks++) {
            const int k0 = ks * 8;
            unsigned a[2][4];
#pragma unroll
            for (int mi = 0; mi < 2; mi++) {
                a[mi][0] = __float_as_uint(S[rowA[mi * 2 + 0] + k0]);
                a[mi][1] = __float_as_uint(S[rowA[mi * 2 + 1] + k0]);
                a[mi][2] = __float_as_uint(S[rowA[mi * 2 + 0] + k0 + 4]);
                a[mi][3] = __float_as_uint(S[rowA[mi * 2 + 1] + k0 + 4]);
            }
#pragma unroll
            for (int ni = 0; ni < 8; ni++) {
                unsigned b0 = __float_as_uint(S[rowB[ni] + k0]);
                unsigned b1 = __float_as_uint(S[rowB[ni] + k0 + 4]);
#pragma unroll
                for (int mi = 0; mi < 2; mi++)
                    mma_tf32(acc[mi][ni], a[mi], b0, b1);
            }
        }
        __syncthreads();
    }
    asm volatile("cp.async.wait_group 0;" ::: "memory");

    // ---- epilogue ----
#pragma unroll
    for (int mi = 0; mi < 2; mi++) {
#pragma unroll
        for (int ni = 0; ni < 8; ni++) {
            const int r = row0 + wm * 32 + mi * 16 + gid;
            const int c = col0 + wn * 64 + ni * 8 + tg * 2;
#pragma unroll
            for (int half = 0; half < 2; half++) {
                const int rr = r + half * 8;
                float v0 = acc[mi][ni][half * 2 + 0];
                float v1 = acc[mi][ni][half * 2 + 1];
                if (MODE == 0) {
                    v0 = round_tf32(fmaxf(v0 + bias[c], 0.f));
                    v1 = round_tf32(fmaxf(v1 + bias[c + 1], 0.f));
                } else if (MODE == 1) {
                    v0 += bias[c];
                    v1 += bias[c + 1];
                } else {
                    float b0 = maskp[c] ? bias2[c] : bias[c];
                    float b1 = maskp[c + 1] ? bias2[c + 1] : bias[c + 1];
                    v0 += b0;  v1 += b1;
                    v0 = round_tf32(v0 / (1.f + __expf(-v0)));
                    v1 = round_tf32(v1 / (1.f + __expf(-v1)));
                }
                *reinterpret_cast<float2*>(&C[(size_t)rr * N + c])
                    = make_float2(v0, v1);
            }
        }
    }
}

// ---------------------------------------------------------------------------
// Top-k machinery (exact radix select + column max) — proven in R1
// ---------------------------------------------------------------------------
__global__ void __launch_bounds__(256)
colmax_hist1_kernel(const float* __restrict__ S2,
                    unsigned* __restrict__ colmax, unsigned* __restrict__ hist)
{
    __shared__ unsigned sh[4096];
    const int bb = blockIdx.x;
    const int b  = bb >> 6;
    const int s0 = (bb & 63) * 16;
    const int t  = threadIdx.x;
    for (int i = t; i < 4096; i += 256) sh[i] = 0;
    __syncthreads();
    float lm[16];
#pragma unroll
    for (int i = 0; i < 16; i++) lm[i] = -3.4e38f;
    for (int s = 0; s < 16; s++) {
        const float* row = S2 + ((size_t)b * SEQ + s0 + s) * HID;
#pragma unroll
        for (int hh = 0; hh < 16; hh++) {
            float f = row[hh * 256 + t];
            lm[hh] = fmaxf(lm[hh], f);
            atomicAdd(&sh[mono(f) >> 20], 1u);
        }
    }
#pragma unroll
    for (int hh = 0; hh < 16; hh++)
        atomicMax(&colmax[b * HID + hh * 256 + t], mono(lm[hh]));
    __syncthreads();
    for (int i = t; i < 4096; i += 256) {
        unsigned c = sh[i];
        if (c) atomicAdd(&hist[b * 4096 + i], c);
    }
}

__global__ void __launch_bounds__(256)
hist_pass2(const float* __restrict__ S2, const unsigned* __restrict__ sel,
           unsigned* __restrict__ hist)
{
    __shared__ unsigned sh[4096];
    const int b = blockIdx.y;
    const int t = threadIdx.x;
    for (int i = t; i < 4096; i += 256) sh[i] = 0;
    __syncthreads();
    const unsigned s1 = sel[b];
    const float4* p = reinterpret_cast<const float4*>(S2 + (size_t)b * NPB)
                      + (size_t)blockIdx.x * 16384;
    for (int i = 0; i < 64; i++) {
        float4 v = p[t + i * 256];
        unsigned u;
        u = mono(v.x); if ((u >> 20) == s1) atomicAdd(&sh[(u >> 8) & 0xFFF], 1u);
        u = mono(v.y); if ((u >> 20) == s1) atomicAdd(&sh[(u >> 8) & 0xFFF], 1u);
        u = mono(v.z); if ((u >> 20) == s1) atomicAdd(&sh[(u >> 8) & 0xFFF], 1u);
        u = mono(v.w); if ((u >> 20) == s1) atomicAdd(&sh[(u >> 8) & 0xFFF], 1u);
    }
    __syncthreads();
    for (int i = t; i < 4096; i += 256) {
        unsigned c = sh[i];
        if (c) atomicAdd(&hist[b * 4096 + i], c);
    }
}

__global__ void __launch_bounds__(256)
hist_pass3(const float* __restrict__ S2, const unsigned* __restrict__ sel,
           unsigned* __restrict__ hist)
{
    __shared__ unsigned sh[256];
    const int b = blockIdx.y;
    const int t = threadIdx.x;
    sh[t] = 0;
    __syncthreads();
    const unsigned s24 = sel[b];
    const float4* p = reinterpret_cast<const float4*>(S2 + (size_t)b * NPB)
                      + (size_t)blockIdx.x * 16384;
    for (int i = 0; i < 64; i++) {
        float4 v = p[t + i * 256];
        unsigned u;
        u = mono(v.x); if ((u >> 8) == s24) atomicAdd(&sh[u & 0xFF], 1u);
        u = mono(v.y); if ((u >> 8) == s24) atomicAdd(&sh[u & 0xFF], 1u);
        u = mono(v.z); if ((u >> 8) == s24) atomicAdd(&sh[u & 0xFF], 1u);
        u = mono(v.w); if ((u >> 8) == s24) atomicAdd(&sh[u & 0xFF], 1u);
    }
    __syncthreads();
    unsigned c = sh[t];
    if (c) atomicAdd(&hist[b * 256 + t], c);
}

__global__ void __launch_bounds__(256)
scan_kernel(const unsigned* __restrict__ hist, int nbins, int stage,
            unsigned* __restrict__ sel, int* __restrict__ krem,
            unsigned* __restrict__ tau)
{
    __shared__ int sS[256];
    __shared__ int sSuf[257];
    const int b = blockIdx.x;
    const int t = threadIdx.x;
    const int k = (stage == 1) ? KSEL : krem[b];
    const int chunk = nbins >> 8;
    const unsigned* h = hist + (size_t)b * nbins;
    int s = 0;
    for (int j = 0; j < chunk; j++) s += h[t * chunk + j];
    sS[t] = s;
    __syncthreads();
    if (t == 0) {
        sSuf[256] = 0;
        for (int i = 255; i >= 0; i--) sSuf[i] = sSuf[i + 1] + sS[i];
    }
    __syncthreads();
    if (sSuf[t] >= k && sSuf[t + 1] < k) {
        int cum = sSuf[t + 1];
        for (int j = chunk - 1; j >= 0; j--) {
            int bin = t * chunk + j;
            int c = (int)h[bin];
            cum += c;
            if (cum >= k) {
                int kp = k - (cum - c);
                if (stage == 1)      { sel[b] = (unsigned)bin; krem[b] = kp; }
                else if (stage == 2) { sel[b] = (sel[b] << 12) | (unsigned)bin; krem[b] = kp; }
                else                 { tau[b] = (sel[b] << 8) | (unsigned)bin; }
                break;
            }
        }
    }
}

__global__ void mask_kernel(const unsigned* __restrict__ colmax,
                            const unsigned* __restrict__ tau,
                            unsigned char* __restrict__ maskarr)
{
    int i = blockIdx.x * 256 + threadIdx.x;   // 32768 total
    maskarr[i] = (colmax[i] >= tau[i >> 12]) ? 1 : 0;
}

// ---------------------------------------------------------------------------
// Host launcher (graph-capturable)
// ---------------------------------------------------------------------------
extern "C" void kernel_launch(void* const* d_in, const int* in_sizes, int n_in,
                              void* d_out, int out_size)
{
    (void)in_sizes; (void)n_in; (void)out_size;
    const float* x     = (const float*)d_in[0];
    const float* up_w  = (const float*)d_in[1];
    const float* up_b  = (const float*)d_in[2];
    const float* gw1   = (const float*)d_in[3];
    const float* gb1   = (const float*)d_in[4];
    const float* gw2   = (const float*)d_in[5];
    const float* gb2   = (const float*)d_in[6];
    const float* mod_w = (const float*)d_in[7];
    const float* mod_b = (const float*)d_in[8];
    const float* dw    = (const float*)d_in[9];
    const float* db    = (const float*)d_in[10];
    float* out = (float*)d_out;

    void *pS1, *pS2, *pH, *pXr, *pG1r, *pG2r, *pUpr, *pModr, *pDwr;
    void *pCol, *pH1, *pH2, *pH3, *pSel, *pK, *pTau, *pMask;
    cudaGetSymbolAddress(&pS1, g_s1);
    cudaGetSymbolAddress(&pS2, g_s2);
    cudaGetSymbolAddress(&pH, g_h);
    cudaGetSymbolAddress(&pXr, g_xr);
    cudaGetSymbolAddress(&pG1r, g_g1r);
    cudaGetSymbolAddress(&pG2r, g_g2r);
    cudaGetSymbolAddress(&pUpr, g_upr);
    cudaGetSymbolAddress(&pModr, g_modr);
    cudaGetSymbolAddress(&pDwr, g_dwr);
    cudaGetSymbolAddress(&pCol, g_colmax);
    cudaGetSymbolAddress(&pH1, g_hist1);
    cudaGetSymbolAddress(&pH2, g_hist2);
    cudaGetSymbolAddress(&pH3, g_hist3);
    cudaGetSymbolAddress(&pSel, g_selbits);
    cudaGetSymbolAddress(&pK, g_krem);
    cudaGetSymbolAddress(&pTau, g_tau);
    cudaGetSymbolAddress(&pMask, g_maskarr);

    cudaMemsetAsync(pCol, 0, BATCH * HID * 4, 0);
    cudaMemsetAsync(pH1, 0, BATCH * 4096 * 4, 0);
    cudaMemsetAsync(pH2, 0, BATCH * 4096 * 4, 0);
    cudaMemsetAsync(pH3, 0, BATCH * 256 * 4, 0);

    // --- one-shot tf32(RNA) rounding of all GEMM operands ---
    {
        int n4;
        n4 = BATCH * SEQ * DMODEL / 4;
        round4_kernel<<<(n4 + 255) / 256, 256>>>((const float4*)x, (float4*)pXr, n4);
        n4 = HID * DMODEL / 4;
        round4_kernel<<<(n4 + 255) / 256, 256>>>((const float4*)gw1, (float4*)pG1r, n4);
        round4_kernel<<<(n4 + 255) / 256, 256>>>((const float4*)up_w, (float4*)pUpr, n4);
        round4_kernel<<<(n4 + 255) / 256, 256>>>((const float4*)mod_w, (float4*)pModr, n4);
        n4 = HID * HID / 4;
        round4_kernel<<<(n4 + 255) / 256, 256>>>((const float4*)gw2, (float4*)pG2r, n4);
        n4 = DMODEL * HID / 4;
        round4_kernel<<<(n4 + 255) / 256, 256>>>((const float4*)dw, (float4*)pDwr, n4);
    }

    cudaFuncSetAttribute(gemm_tf32<0>, cudaFuncAttributeMaxDynamicSharedMemorySize, SMEM_BYTES);
    cudaFuncSetAttribute(gemm_tf32<1>, cudaFuncAttributeMaxDynamicSharedMemorySize, SMEM_BYTES);
    cudaFuncSetAttribute(gemm_tf32<2>, cudaFuncAttributeMaxDynamicSharedMemorySize, SMEM_BYTES);

    // GEMM1: S1 = relu(X @ gw1^T + gb1), tf32-rounded out  [8192 x 4096] K=1024
    gemm_tf32<0><<<dim3(HID / BN, (BATCH * SEQ) / BM, 1), 256, SMEM_BYTES>>>(
        (const float*)pXr, (const float*)pG1r, nullptr, gb1, nullptr, nullptr,
        (float*)pS1, BATCH * SEQ, HID, DMODEL);

    // GEMM2: S2 = S1 @ gw2^T + gb2  [8192 x 4096] K=4096
    gemm_tf32<1><<<dim3(HID / BN, (BATCH * SEQ) / BM, 1), 256, SMEM_BYTES>>>(
        (const float*)pS1, (const float*)pG2r, nullptr, gb2, nullptr, nullptr,
        (float*)pS2, BATCH * SEQ, HID, HID);

    // Exact k-th largest per batch + mask
    colmax_hist1_kernel<<<BATCH * 64, 256>>>(
        (const float*)pS2, (unsigned*)pCol, (unsigned*)pH1);
    scan_kernel<<<BATCH, 256>>>((const unsigned*)pH1, 4096, 1,
                                (unsigned*)pSel, (int*)pK, (unsigned*)pTau);
    hist_pass2<<<dim3(64, BATCH), 256>>>(
        (const float*)pS2, (const unsigned*)pSel, (unsigned*)pH2);
    scan_kernel<<<BATCH, 256>>>((const unsigned*)pH2, 4096, 2,
                                (unsigned*)pSel, (int*)pK, (unsigned*)pTau);
    hist_pass3<<<dim3(64, BATCH), 256>>>(
        (const float*)pS2, (const unsigned*)pSel, (unsigned*)pH3);
    scan_kernel<<<BATCH, 256>>>((const unsigned*)pH3, 256, 3,
                                (unsigned*)pSel, (int*)pK, (unsigned*)pTau);
    mask_kernel<<<128, 256>>>((const unsigned*)pCol, (const unsigned*)pTau,
                              (unsigned char*)pMask);

    // GEMM3 (per batch): h = silu(X_b @ Wsel^T + bsel), tf32-rounded out
    gemm_tf32<2><<<dim3(HID / BN, SEQ / BM, BATCH), 256, SMEM_BYTES>>>(
        (const float*)pXr, (const float*)pUpr, (const float*)pModr,
        up_b, mod_b, (const unsigned char*)pMask,
        (float*)pH, SEQ, HID, DMODEL);

    // GEMM4: out = h @ dw^T + db  [8192 x 1024] K=4096
    gemm_tf32<1><<<dim3(DMODEL / BN, (BATCH * SEQ) / BM, 1), 256, SMEM_BYTES>>>(
        (const float*)pH, (const float*)pDwr, nullptr, db, nullptr, nullptr,
        out, BATCH * SEQ, DMODEL, HID);
}